// round 15
// baseline (speedup 1.0000x reference)
#include <cuda_runtime.h>
#include <cuda_fp16.h>
#include <math.h>
#include <stdint.h>

#define Hd   1024
#define Bb   8
#define Pp   64
#define Ee   3
#define RHd  2048
#define BT   16384
#define C2H  2048
#define CK6  6144
#define CUP  7168

// ===========================================================================
// PTX helpers
// ===========================================================================
__device__ __forceinline__ uint32_t smem_u32(const void* p){
    uint32_t a;
    asm("{ .reg .u64 t; cvta.to.shared.u64 t, %1; cvt.u32.u64 %0, t; }" : "=r"(a) : "l"(p));
    return a;
}
#define CPA(dst, src) asm volatile("cp.async.cg.shared.global [%0], [%1], 16;" :: "r"(dst), "l"(src))
#define CPC()  asm volatile("cp.async.commit_group;" ::: "memory")
#define CPW2() asm volatile("cp.async.wait_group 2;" ::: "memory")
#define CPW0() asm volatile("cp.async.wait_group 0;" ::: "memory")

__device__ __forceinline__ void ldsm4(uint32_t* r, uint32_t addr){
    asm("ldmatrix.sync.aligned.m8n8.x4.shared.b16 {%0,%1,%2,%3}, [%4];"
        : "=r"(r[0]), "=r"(r[1]), "=r"(r[2]), "=r"(r[3]) : "r"(addr) : "memory");
}
__device__ __forceinline__ void mma16816(float* d, const uint32_t* a, const uint32_t* b){
    asm("mma.sync.aligned.m16n8k16.row.col.f32.f16.f16.f32 "
        "{%0,%1,%2,%3}, {%4,%5,%6,%7}, {%8,%9}, {%0,%1,%2,%3};"
        : "+f"(d[0]), "+f"(d[1]), "+f"(d[2]), "+f"(d[3])
        : "r"(a[0]), "r"(a[1]), "r"(a[2]), "r"(a[3]), "r"(b[0]), "r"(b[1]));
}

__device__ __forceinline__ float siluf(float x){ return x / (1.0f + expf(-x)); }
__device__ __forceinline__ float sigmf(float x){ return 1.0f / (1.0f + expf(-x)); }

// ===========================================================================
// Scratch
// ===========================================================================
#define DC ((size_t)BT * C2H)
#define DH ((size_t)BT * CUP)
#define D1 ((size_t)BT * Hd)
#define DP ((size_t)Bb * Pp * Hd)

__device__ __half g_c[DC];
__device__ __half g_h[DH];
__device__ __half g_r[D1];
__device__ __half g_p[DP];
__device__ float g_q[(size_t)BT * Hd];
__device__ float g_kv[(size_t)Bb * Pp * C2H];
__device__ float g_gate[(size_t)BT * Hd];
__device__ float g_probs[(size_t)BT * Ee];
__device__ float g_aux[4*8*2048 + 8*3];
#define AUX_ARL 65536

#define WQ_OFF   ((size_t)0)
#define WK_OFF   (WQ_OFF  + (size_t)Hd*Hd)
#define WV_OFF   (WK_OFF  + (size_t)Hd*Hd)
#define GW2_OFF  (WV_OFF  + (size_t)Hd*Hd)
#define OW_OFF   (GW2_OFF + (size_t)Hd*Hd)
#define UP_OFF   (OW_OFF  + (size_t)Hd*Hd)
#define EW2_OFF  (UP_OFF  + (size_t)CUP*C2H)
#define WT_TOTAL (EW2_OFF + (size_t)Hd*CK6)
__device__ __half g_wT[WT_TOTAL];

// ===========================================================================
// Fused weight prep
// ===========================================================================
__global__ __launch_bounds__(256)
void prep_weights(const float* __restrict__ Wq, const float* __restrict__ Wk,
                  const float* __restrict__ Wv, const float* __restrict__ gw1,
                  const float* __restrict__ gw2, const float* __restrict__ outw,
                  const float* __restrict__ ew1, const float* __restrict__ ew2,
                  __half* __restrict__ T)
{
    int t = blockIdx.x;
    const float* W; int N, ldT, koff, tilesN; size_t dst;
    if (t < 3072) {
        int m = t >> 10; t &= 1023;
        W = (m == 0) ? Wq : ((m == 1) ? Wk : Wv);
        N = 1024; ldT = 1024; koff = 0; dst = (size_t)m * Hd * Hd; tilesN = 32;
    } else if (t < 4096) {
        t -= 3072; W = gw2; N = 1024; ldT = 1024; koff = 0; dst = GW2_OFF; tilesN = 32;
    } else if (t < 5120) {
        t -= 4096; W = outw; N = 1024; ldT = 1024; koff = 0; dst = OW_OFF; tilesN = 32;
    } else if (t < 17408) {
        t -= 5120; int e = t >> 12; t &= 4095;
        W = ew1 + (size_t)e * 3072 * RHd; N = RHd; ldT = C2H; koff = 0;
        dst = UP_OFF + (size_t)e * RHd * C2H; tilesN = 64;
    } else if (t < 19456) {
        t -= 17408; W = gw1; N = 1024; ldT = C2H; koff = 0;
        dst = UP_OFF + (size_t)6144 * C2H; tilesN = 32;
    } else {
        t -= 19456; int e = t >> 11; t &= 2047;
        W = ew2 + (size_t)e * RHd * Hd; N = 1024; ldT = CK6; koff = e * RHd;
        dst = EW2_OFF; tilesN = 32;
    }
    const int tn = t & (tilesN - 1);
    const int tk = (tilesN == 64) ? (t >> 6) : (t >> 5);
    const int n0 = tn * 32, k0 = tk * 32;

    __shared__ float tt[32][33];
    const int tx = threadIdx.x & 31, ty = threadIdx.x >> 5;
#pragma unroll
    for (int i = 0; i < 4; ++i)
        tt[ty + i * 8][tx] = W[(size_t)(k0 + ty + i * 8) * N + n0 + tx];
    __syncthreads();
    __half* Th = T + dst;
#pragma unroll
    for (int i = 0; i < 4; ++i) {
        float v = tt[tx][ty + i * 8];
        size_t o = (size_t)(n0 + ty + i * 8) * ldT + koff + k0 + tx;
        Th[o] = __float2half_rn(v);
    }
}

__global__ __launch_bounds__(256)
void split_hi(const float* __restrict__ src, __half* __restrict__ h, int n)
{
    int i = blockIdx.x * 256 + threadIdx.x;
    if (i < n) h[i] = __float2half_rn(src[i]);
}

// ===========================================================================
// Anchor-folded terms + biases
// ===========================================================================
__global__ __launch_bounds__(256)
void anchor_pre(const float* __restrict__ anchor,
                const float* __restrict__ ew1, const float* __restrict__ eb1,
                const float* __restrict__ gw1, const float* __restrict__ gb1,
                const float* __restrict__ routerW, const float* __restrict__ routerB,
                float* __restrict__ aux)
{
    const int b = blockIdx.y;
    const int j = blockIdx.x * 256 + threadIdx.x;
    __shared__ float as[Hd];
    for (int i = threadIdx.x; i < Hd; i += 256) as[i] = anchor[(size_t)b * Hd + i];
    __syncthreads();
    if (j >= 4*2048 + Ee) return;
    const float* wp; int stride; float* outp; float bia;
    if (j < 4*2048) {
        int pe = j >> 11, col = j & 2047;
        if (pe < 3) {
            wp = ew1 + (size_t)pe*3072*RHd + (size_t)2048*RHd + col; stride = RHd;
            bia = eb1[(size_t)pe * RHd + col];
        } else {
            if (col >= Hd) return;
            wp = gw1 + (size_t)2048*Hd + col; stride = Hd;
            bia = gb1[col];
        }
        outp = aux + (size_t)(pe*8 + b)*2048 + col;
    } else {
        int col = j - 4*2048;
        wp = routerW + (size_t)2048*Ee + col; stride = Ee;
        bia = routerB[col];
        outp = aux + AUX_ARL + b*Ee + col;
    }
    float acc = bia;
#pragma unroll 4
    for (int kk = 0; kk < Hd; ++kk) acc += as[kk] * wp[(size_t)kk * stride];
    *outp = acc;
}

// ===========================================================================
// LayerNorm (fp16 out only)
// ===========================================================================
__global__ __launch_bounds__(256)
void ln_kernel(const float* __restrict__ x,
               const float* __restrict__ gamma,
               const float* __restrict__ beta,
               __half* __restrict__ chi)
{
    const int row = blockIdx.x;
    const int tid = threadIdx.x;
    const float* xr = x + (size_t)row * Hd;

    float v[4];
    float s = 0.f, s2 = 0.f;
#pragma unroll
    for (int i = 0; i < 4; ++i) {
        v[i] = xr[tid + i * 256];
        s += v[i]; s2 += v[i] * v[i];
    }
    __shared__ float red0[8], red1[8];
    const int lane = tid & 31, wid = tid >> 5;
#pragma unroll
    for (int o = 16; o > 0; o >>= 1) {
        s  += __shfl_xor_sync(0xffffffffu, s, o);
        s2 += __shfl_xor_sync(0xffffffffu, s2, o);
    }
    if (lane == 0) { red0[wid] = s; red1[wid] = s2; }
    __syncthreads();
    __shared__ float s_mean, s_rstd;
    if (tid == 0) {
        float ts = 0.f, ts2 = 0.f;
#pragma unroll
        for (int i = 0; i < 8; ++i) { ts += red0[i]; ts2 += red1[i]; }
        float mean = ts * (1.0f / Hd);
        float var  = ts2 * (1.0f / Hd) - mean * mean;
        s_mean = mean; s_rstd = rsqrtf(var + 1e-5f);
    }
    __syncthreads();
    const float mean = s_mean, rstd = s_rstd;

    __half* hrow = chi + (size_t)row * C2H;
#pragma unroll
    for (int i = 0; i < 4; ++i) {
        int c = tid + i * 256;
        float nx = (v[i] - mean) * rstd * gamma[c] + beta[c];
        hrow[c] = __float2half_rn(nx);
    }
}

// ===========================================================================
// Cross-attention, 8 tokens / block (fp16 evidence out only)
// ===========================================================================
__global__ __launch_bounds__(256)
void attn8_kernel(const float* __restrict__ q,
                  const float* __restrict__ kv,
                  __half* __restrict__ chi)
{
    const int t0  = blockIdx.x * 8;
    const int b   = t0 >> 11;
    const int tid = threadIdx.x;
    const int lane = tid & 31, w = tid >> 5;

    __shared__ float qs[8][Hd];
    __shared__ float sc[8][Pp];

    for (int i = tid; i < 8 * Hd; i += 256)
        qs[i >> 10][i & 1023] = q[(size_t)(t0 + (i >> 10)) * Hd + (i & 1023)];
    __syncthreads();

    const float* kvb = kv + (size_t)b * Pp * C2H;
    for (int p = w; p < Pp; p += 8) {
        const float* kr = kvb + (size_t)p * C2H;
        float d[8];
#pragma unroll
        for (int t = 0; t < 8; ++t) d[t] = 0.f;
        for (int i = lane; i < Hd; i += 32) {
            float kvv = kr[i];
#pragma unroll
            for (int t = 0; t < 8; ++t) d[t] += kvv * qs[t][i];
        }
#pragma unroll
        for (int t = 0; t < 8; ++t) {
#pragma unroll
            for (int o = 16; o > 0; o >>= 1)
                d[t] += __shfl_xor_sync(0xffffffffu, d[t], o);
        }
        if (lane == 0) {
#pragma unroll
            for (int t = 0; t < 8; ++t) sc[t][p] = d[t] * 0.03125f;
        }
    }
    __syncthreads();

    {
        float a = sc[w][lane], c = sc[w][lane + 32];
        float m = fmaxf(a, c);
#pragma unroll
        for (int o = 16; o > 0; o >>= 1) m = fmaxf(m, __shfl_xor_sync(0xffffffffu, m, o));
        float e1 = expf(a - m), e2 = expf(c - m);
        float ssum = e1 + e2;
#pragma unroll
        for (int o = 16; o > 0; o >>= 1) ssum += __shfl_xor_sync(0xffffffffu, ssum, o);
        float inv = 1.0f / ssum;
        sc[w][lane] = e1 * inv; sc[w][lane + 32] = e2 * inv;
    }
    __syncthreads();

    const int c0 = tid * 4;
    const float* vb = kvb + Hd + c0;
    float acc[8][4];
#pragma unroll
    for (int t = 0; t < 8; ++t)
#pragma unroll
        for (int j = 0; j < 4; ++j) acc[t][j] = 0.f;
    for (int p = 0; p < Pp; ++p) {
        float4 vv = *(const float4*)(vb + (size_t)p * C2H);
#pragma unroll
        for (int t = 0; t < 8; ++t) {
            float wt = sc[t][p];
            acc[t][0] += wt * vv.x; acc[t][1] += wt * vv.y;
            acc[t][2] += wt * vv.z; acc[t][3] += wt * vv.w;
        }
    }
#pragma unroll
    for (int t = 0; t < 8; ++t) {
        size_t base = (size_t)(t0 + t) * C2H + Hd + c0;
#pragma unroll
        for (int j = 0; j < 4; ++j)
            chi[base + j] = __float2half_rn(acc[t][j]);
    }
}

// ===========================================================================
// Router (reads fp16 combined)
// ===========================================================================
__global__ __launch_bounds__(128)
void router_kernel(const __half* __restrict__ chi,
                   const float* __restrict__ W,
                   const float* __restrict__ aux,
                   float* __restrict__ probs)
{
    const int row = blockIdx.x;
    const int b   = row >> 11;
    const int tid = threadIdx.x;
    const int lane = tid & 31, w = tid >> 5;
    __shared__ float lg[Ee];

    if (w < Ee) {
        const __half* cr = chi + (size_t)row * C2H;
        float d = 0.f;
        for (int i = lane; i < C2H; i += 32)
            d += __half2float(cr[i]) * W[(size_t)i * Ee + w];
#pragma unroll
        for (int o = 16; o > 0; o >>= 1) d += __shfl_xor_sync(0xffffffffu, d, o);
        if (lane == 0) lg[w] = d + aux[AUX_ARL + b*Ee + w];
    }
    __syncthreads();
    if (tid == 0) {
        float m = fmaxf(lg[0], fmaxf(lg[1], lg[2]));
        float e0 = expf(lg[0] - m), e1 = expf(lg[1] - m), e2 = expf(lg[2] - m);
        float inv = 1.0f / (e0 + e1 + e2);
        probs[(size_t)row * Ee + 0] = e0 * inv;
        probs[(size_t)row * Ee + 1] = e1 * inv;
        probs[(size_t)row * Ee + 2] = e2 * inv;
    }
}

// ===========================================================================
// mma.sync pure-fp16 GEMM. CTA 128x128, 8 warps, Ktile=32, 64B rows + XOR
// swizzle. 6-stage ring (16KB/stage, 96KB/CTA, 2 CTAs/SM); ONE __syncthreads
// per 2 K-tiles. Pair reads stages {it,it+1}; issues {(it+4)%6,(it+5)%6}
// (= last pair's read stages, retired by the barrier).
// ===========================================================================
#define MAT_SZ   8192
#define STG_SZ   16384
#define SMEM_DYN 98304

template<int EPI>
__global__ __launch_bounds__(256, 2)
void mma_gemm(const __half* __restrict__ Ahi, int lda,
              const __half* __restrict__ Bhi, int K,
              float* __restrict__ C, int ldc,
              __half* __restrict__ Chi,
              const float* __restrict__ bias,
              const float* __restrict__ extra,
              const float* __restrict__ prob,
              const float* __restrict__ gate,
              const float* __restrict__ resid)
{
    extern __shared__ char smem[];
    const uint32_t sb = smem_u32(smem);

    const int tid  = threadIdx.x;
    const int lane = tid & 31, wid = tid >> 5;
    const int bm = blockIdx.y * 128, bn = blockIdx.x * 128;
    const int m0 = (wid >> 1) * 32, n0 = (wid & 1) * 64;

    const int rowA = tid >> 2, segA = tid & 3;
    const char* gA = (const char*)(Ahi + (size_t)(bm + rowA) * lda + segA * 8);
    const char* gB = (const char*)(Bhi + (size_t)(bn + rowA) * K + segA * 8);
    const size_t oA64 = (size_t)lda * 128;
    const size_t oB64 = (size_t)K * 128;
    const uint32_t sd0 = sb + rowA * 64 + ((segA ^ ((rowA >> 1) & 3)) << 4);

    const int NC = K >> 5;   // always even (K multiple of 64)

#define ISSUE(it, so_) do{ \
        if ((it) < NC) { \
            uint32_t d_ = sd0 + (so_); \
            CPA(d_,                  gA); \
            CPA(d_ + 4096,           gA + oA64); \
            CPA(d_ + MAT_SZ,         gB); \
            CPA(d_ + MAT_SZ + 4096,  gB + oB64); \
            gA += 64; gB += 64; \
        } \
        CPC(); \
    } while(0)

    ISSUE(0, 0);
    ISSUE(1, STG_SZ);
    ISSUE(2, 2*STG_SZ);
    ISSUE(3, 3*STG_SZ);

    float acc[2][8][4];
#pragma unroll
    for (int mi = 0; mi < 2; ++mi)
#pragma unroll
        for (int nt = 0; nt < 8; ++nt)
#pragma unroll
            for (int r = 0; r < 4; ++r) acc[mi][nt][r] = 0.f;

    const int arow = m0 + (lane & 15);
    const uint32_t abc = (uint32_t)(lane >> 4);
    uint32_t aro[2], asw[2];
#pragma unroll
    for (int mi = 0; mi < 2; ++mi) {
        int r = arow + mi * 16;
        aro[mi] = (uint32_t)(r * 64);
        asw[mi] = (uint32_t)((r >> 1) & 3);
    }
    const int brow = n0 + ((lane >> 4) & 1) * 8 + (lane & 7);
    const uint32_t bbc = (uint32_t)((lane >> 3) & 1);
    uint32_t bro[4], bsw[4];
#pragma unroll
    for (int p = 0; p < 4; ++p) {
        int r = brow + p * 16;
        bro[p] = (uint32_t)(MAT_SZ + r * 64);
        bsw[p] = (uint32_t)((r >> 1) & 3);
    }

#define COMPUTE(rsoff) do{ \
        const uint32_t stg_ = sb + (rsoff); \
        _Pragma("unroll") \
        for (int ks = 0; ks < 2; ++ks) { \
            const uint32_t ks2 = (uint32_t)(ks << 1); \
            uint32_t ah[2][4]; \
            _Pragma("unroll") \
            for (int mi = 0; mi < 2; ++mi) { \
                uint32_t ad = stg_ + aro[mi] + (((abc | ks2) ^ asw[mi]) << 4); \
                ldsm4(ah[mi], ad); \
            } \
            uint32_t bh[16]; \
            _Pragma("unroll") \
            for (int p = 0; p < 4; ++p) { \
                uint32_t bd = stg_ + bro[p] + (((bbc | ks2) ^ bsw[p]) << 4); \
                ldsm4(bh + p * 4, bd); \
            } \
            _Pragma("unroll") \
            for (int mi = 0; mi < 2; ++mi) \
                _Pragma("unroll") \
                for (int nt = 0; nt < 8; ++nt) \
                    mma16816(acc[mi][nt], ah[mi], bh + nt * 2); \
        } \
    } while(0)

    uint32_t rs = 0, ws = 4 * STG_SZ;
    for (int it = 0; it < NC; it += 2) {
        CPW2();
        __syncthreads();
        ISSUE(it + 4, ws); ws += STG_SZ; if (ws == 6*STG_SZ) ws = 0;
        ISSUE(it + 5, ws); ws += STG_SZ; if (ws == 6*STG_SZ) ws = 0;
        COMPUTE(rs); rs += STG_SZ; if (rs == 6*STG_SZ) rs = 0;
        COMPUTE(rs); rs += STG_SZ; if (rs == 6*STG_SZ) rs = 0;
    }
    CPW0();

    // ---- epilogue ----
    const int pe = bn >> 11;
#pragma unroll
    for (int nt = 0; nt < 8; ++nt) {
        const int col = bn + n0 + nt * 8 + (lane & 3) * 2;
        float bia0 = 0.f, bia1 = 0.f;
        if (EPI == 3 || EPI == 4) { bia0 = bias[col]; bia1 = bias[col + 1]; }
#pragma unroll
        for (int mi = 0; mi < 2; ++mi) {
#pragma unroll
            for (int hf = 0; hf < 2; ++hf) {
                const int row = bm + m0 + mi * 16 + (lane >> 2) + hf * 8;
                float v0 = acc[mi][nt][hf * 2 + 0];
                float v1 = acc[mi][nt][hf * 2 + 1];
                const size_t off = (size_t)row * ldc + col;
                if (EPI == 0) {
                    *(float2*)(C + off) = make_float2(v0, v1);
                } else if (EPI == 1) {
                    const int b = row >> 11;
                    const float* ex = extra + ((size_t)(pe * 8 + b) << 11) + (col & 2047);
                    float s0 = siluf(v0 + ex[0]);
                    float s1 = siluf(v1 + ex[1]);
                    if (pe < 3) {
                        float p = prob[(size_t)row * Ee + pe];
                        s0 *= p; s1 *= p;
                    }
                    __half2 hv; hv.x = __float2half_rn(s0); hv.y = __float2half_rn(s1);
                    *(__half2*)(Chi + off) = hv;
                } else if (EPI == 2) {
                    float p0 = prob[(size_t)row * Ee + 0];
                    float p1 = prob[(size_t)row * Ee + 1];
                    float p2 = prob[(size_t)row * Ee + 2];
                    float u0 = v0 + p0*bias[col]   + p1*bias[Hd+col]   + p2*bias[2*Hd+col];
                    float u1 = v1 + p0*bias[col+1] + p1*bias[Hd+col+1] + p2*bias[2*Hd+col+1];
                    __half2 hv; hv.x = __float2half_rn(u0); hv.y = __float2half_rn(u1);
                    *(__half2*)(Chi + off) = hv;
                } else if (EPI == 3) {
                    *(float2*)(C + off) = make_float2(sigmf(v0 + bia0), sigmf(v1 + bia1));
                } else {
                    float2 gg = *(const float2*)(gate + off);
                    float2 xx = *(const float2*)(resid + off);
                    *(float2*)(C + off) =
                        make_float2(xx.x + gg.x * (v0 + bia0), xx.y + gg.y * (v1 + bia1));
                }
            }
        }
    }
#undef ISSUE
#undef COMPUTE
}

// ===========================================================================
// Launch  (4th launch = q-projection GEMM — profiler capture)
// ===========================================================================
extern "C" void kernel_launch(void* const* d_in, const int* in_sizes, int n_in,
                              void* d_out, int out_size)
{
    const float* x       = (const float*)d_in[0];
    const float* anchor  = (const float*)d_in[1];
    const float* proto   = (const float*)d_in[2];
    const float* gamma   = (const float*)d_in[3];
    const float* beta    = (const float*)d_in[4];
    const float* Wq      = (const float*)d_in[5];
    const float* Wk      = (const float*)d_in[6];
    const float* Wv      = (const float*)d_in[7];
    const float* routerW = (const float*)d_in[8];
    const float* routerB = (const float*)d_in[9];
    const float* ew1     = (const float*)d_in[10];
    const float* eb1     = (const float*)d_in[11];
    const float* ew2     = (const float*)d_in[12];
    const float* eb2     = (const float*)d_in[13];
    const float* gw1     = (const float*)d_in[14];
    const float* gb1     = (const float*)d_in[15];
    const float* gw2     = (const float*)d_in[16];
    const float* gb2     = (const float*)d_in[17];
    const float* outw    = (const float*)d_in[18];
    const float* outb    = (const float*)d_in[19];
    float* out = (float*)d_out;

    float *q, *kv, *gate, *probs, *aux;
    __half *c2, *h2, *r2, *p2, *wt;
    cudaGetSymbolAddress((void**)&c2, g_c);
    cudaGetSymbolAddress((void**)&h2, g_h);
    cudaGetSymbolAddress((void**)&r2, g_r);
    cudaGetSymbolAddress((void**)&p2, g_p);
    cudaGetSymbolAddress((void**)&q, g_q);
    cudaGetSymbolAddress((void**)&kv, g_kv);
    cudaGetSymbolAddress((void**)&gate, g_gate);
    cudaGetSymbolAddress((void**)&probs, g_probs);
    cudaGetSymbolAddress((void**)&aux, g_aux);
    cudaGetSymbolAddress((void**)&wt, g_wT);

    cudaFuncSetAttribute((const void*)mma_gemm<0>, cudaFuncAttributeMaxDynamicSharedMemorySize, SMEM_DYN);
    cudaFuncSetAttribute((const void*)mma_gemm<1>, cudaFuncAttributeMaxDynamicSharedMemorySize, SMEM_DYN);
    cudaFuncSetAttribute((const void*)mma_gemm<2>, cudaFuncAttributeMaxDynamicSharedMemorySize, SMEM_DYN);
    cudaFuncSetAttribute((const void*)mma_gemm<3>, cudaFuncAttributeMaxDynamicSharedMemorySize, SMEM_DYN);
    cudaFuncSetAttribute((const void*)mma_gemm<4>, cudaFuncAttributeMaxDynamicSharedMemorySize, SMEM_DYN);

    // 1: fused weight prep
    prep_weights<<<25600, 256>>>(Wq, Wk, Wv, gw1, gw2, outw, ew1, ew2, wt);
    // 2: LayerNorm
    ln_kernel<<<BT, 256>>>(x, gamma, beta, c2);
    // 3: prototype hi split
    split_hi<<<(Bb*Pp*Hd + 255)/256, 256>>>(proto, p2, Bb*Pp*Hd);
    // 4: q projection (K=Hd)   <-- profiler capture position
    mma_gemm<0><<<dim3(Hd/128, BT/128), 256, SMEM_DYN>>>(
        c2, C2H, wt + WQ_OFF, Hd,
        q, Hd, nullptr, nullptr, nullptr, nullptr, nullptr, nullptr);
    // 5: fused k|v projection (N=2048)
    mma_gemm<0><<<dim3(C2H/128, (Bb*Pp)/128), 256, SMEM_DYN>>>(
        p2, Hd, wt + WK_OFF, Hd,
        kv, C2H, nullptr, nullptr, nullptr, nullptr, nullptr, nullptr);
    // 6: attention (8 tokens / block)
    attn8_kernel<<<BT/8, 256>>>(q, kv, c2);
    // 7: anchor folding (+ biases)
    anchor_pre<<<dim3(33, Bb), 256>>>(anchor, ew1, eb1, gw1, gb1, routerW, routerB, aux);
    // 8: router (fp16 combined)
    router_kernel<<<BT, 128>>>(c2, routerW, aux, probs);
    // 9: fused up-projection [experts*3 | gate1] (N=7168)
    mma_gemm<1><<<dim3(CUP/128, BT/128), 256, SMEM_DYN>>>(
        c2, C2H, wt + UP_OFF, C2H,
        nullptr, CUP, h2, nullptr, aux, probs, nullptr, nullptr);
    // 10: fused expert down (K=6144, lda=7168)
    mma_gemm<2><<<dim3(Hd/128, BT/128), 256, SMEM_DYN>>>(
        h2, CUP, wt + EW2_OFF, CK6,
        nullptr, Hd, r2, eb2, nullptr, probs, nullptr, nullptr);
    // 11: gate2 (K=1024, A = gate block of h')
    mma_gemm<3><<<dim3(Hd/128, BT/128), 256, SMEM_DYN>>>(
        h2 + 6144, CUP, wt + GW2_OFF, Hd,
        gate, Hd, nullptr, gb2, nullptr, nullptr, nullptr, nullptr);
    // 12: final
    mma_gemm<4><<<dim3(Hd/128, BT/128), 256, SMEM_DYN>>>(
        r2, Hd, wt + OW_OFF, Hd,
        out, Hd, nullptr, outb, nullptr, nullptr, gate, x);
}

// round 17
// speedup vs baseline: 1.0611x; 1.0611x over previous
#include <cuda_runtime.h>
#include <cuda_fp16.h>
#include <math.h>
#include <stdint.h>

#define Hd   1024
#define Bb   8
#define Pp   64
#define Ee   3
#define RHd  2048
#define BT   16384
#define C2H  2048
#define CK6  6144
#define CUP  7168

// ===========================================================================
// PTX helpers
// ===========================================================================
__device__ __forceinline__ uint32_t smem_u32(const void* p){
    uint32_t a;
    asm("{ .reg .u64 t; cvta.to.shared.u64 t, %1; cvt.u32.u64 %0, t; }" : "=r"(a) : "l"(p));
    return a;
}
#define CPA(dst, src) asm volatile("cp.async.cg.shared.global [%0], [%1], 16;" :: "r"(dst), "l"(src))
#define CPC()  asm volatile("cp.async.commit_group;" ::: "memory")
#define CPW2() asm volatile("cp.async.wait_group 2;" ::: "memory")
#define CPW0() asm volatile("cp.async.wait_group 0;" ::: "memory")

__device__ __forceinline__ void ldsm4(uint32_t* r, uint32_t addr){
    asm("ldmatrix.sync.aligned.m8n8.x4.shared.b16 {%0,%1,%2,%3}, [%4];"
        : "=r"(r[0]), "=r"(r[1]), "=r"(r[2]), "=r"(r[3]) : "r"(addr) : "memory");
}
__device__ __forceinline__ void mma16816(float* d, const uint32_t* a, const uint32_t* b){
    asm("mma.sync.aligned.m16n8k16.row.col.f32.f16.f16.f32 "
        "{%0,%1,%2,%3}, {%4,%5,%6,%7}, {%8,%9}, {%0,%1,%2,%3};"
        : "+f"(d[0]), "+f"(d[1]), "+f"(d[2]), "+f"(d[3])
        : "r"(a[0]), "r"(a[1]), "r"(a[2]), "r"(a[3]), "r"(b[0]), "r"(b[1]));
}

__device__ __forceinline__ float siluf(float x){ return x / (1.0f + expf(-x)); }
__device__ __forceinline__ float sigmf(float x){ return 1.0f / (1.0f + expf(-x)); }

// ===========================================================================
// Scratch
// ===========================================================================
#define DC ((size_t)BT * C2H)
#define DH ((size_t)BT * CUP)
#define D1 ((size_t)BT * Hd)
#define DP ((size_t)Bb * Pp * Hd)

__device__ __half g_c[DC];
__device__ __half g_h[DH];
__device__ __half g_r[D1];
__device__ __half g_p[DP];
__device__ float g_q[(size_t)BT * Hd];
__device__ float g_kv[(size_t)Bb * Pp * C2H];
__device__ float g_gate[(size_t)BT * Hd];
__device__ float g_probs[(size_t)BT * Ee];
__device__ float g_aux[4*8*2048 + 8*3];
#define AUX_ARL 65536

#define WQ_OFF   ((size_t)0)
#define WK_OFF   (WQ_OFF  + (size_t)Hd*Hd)
#define WV_OFF   (WK_OFF  + (size_t)Hd*Hd)
#define GW2_OFF  (WV_OFF  + (size_t)Hd*Hd)
#define OW_OFF   (GW2_OFF + (size_t)Hd*Hd)
#define UP_OFF   (OW_OFF  + (size_t)Hd*Hd)
#define EW2_OFF  (UP_OFF  + (size_t)CUP*C2H)
#define WT_TOTAL (EW2_OFF + (size_t)Hd*CK6)
__device__ __half g_wT[WT_TOTAL];

// ===========================================================================
// Fused setup: prep_weights ∪ LayerNorm ∪ split_hi ∪ anchor_pre
// ===========================================================================
#define SU_PREP 25600
#define SU_LN   41984
#define SU_SPL  44032
#define SU_ANC  44296

__global__ __launch_bounds__(256)
void setup_all(const float* __restrict__ x,
               const float* __restrict__ gamma, const float* __restrict__ beta,
               const float* __restrict__ proto, const float* __restrict__ anchor,
               const float* __restrict__ Wq, const float* __restrict__ Wk,
               const float* __restrict__ Wv,
               const float* __restrict__ routerW, const float* __restrict__ routerB,
               const float* __restrict__ ew1, const float* __restrict__ eb1,
               const float* __restrict__ ew2,
               const float* __restrict__ gw1, const float* __restrict__ gb1,
               const float* __restrict__ gw2,
               const float* __restrict__ outw,
               __half* __restrict__ T, __half* __restrict__ chi,
               __half* __restrict__ p2, float* __restrict__ aux)
{
    const int bid = blockIdx.x;
    const int tid = threadIdx.x;

    if (bid < SU_PREP) {
        int t = bid;
        const float* W; int N, ldT, koff, tilesN; size_t dst;
        if (t < 3072) {
            int m = t >> 10; t &= 1023;
            W = (m == 0) ? Wq : ((m == 1) ? Wk : Wv);
            N = 1024; ldT = 1024; koff = 0; dst = (size_t)m * Hd * Hd; tilesN = 32;
        } else if (t < 4096) {
            t -= 3072; W = gw2; N = 1024; ldT = 1024; koff = 0; dst = GW2_OFF; tilesN = 32;
        } else if (t < 5120) {
            t -= 4096; W = outw; N = 1024; ldT = 1024; koff = 0; dst = OW_OFF; tilesN = 32;
        } else if (t < 17408) {
            t -= 5120; int e = t >> 12; t &= 4095;
            W = ew1 + (size_t)e * 3072 * RHd; N = RHd; ldT = C2H; koff = 0;
            dst = UP_OFF + (size_t)e * RHd * C2H; tilesN = 64;
        } else if (t < 19456) {
            t -= 17408; W = gw1; N = 1024; ldT = C2H; koff = 0;
            dst = UP_OFF + (size_t)6144 * C2H; tilesN = 32;
        } else {
            t -= 19456; int e = t >> 11; t &= 2047;
            W = ew2 + (size_t)e * RHd * Hd; N = 1024; ldT = CK6; koff = e * RHd;
            dst = EW2_OFF; tilesN = 32;
        }
        const int tn = t & (tilesN - 1);
        const int tk = (tilesN == 64) ? (t >> 6) : (t >> 5);
        const int n0 = tn * 32, k0 = tk * 32;

        __shared__ float tt[32][33];
        const int tx = tid & 31, ty = tid >> 5;
#pragma unroll
        for (int i = 0; i < 4; ++i)
            tt[ty + i * 8][tx] = W[(size_t)(k0 + ty + i * 8) * N + n0 + tx];
        __syncthreads();
        __half* Th = T + dst;
#pragma unroll
        for (int i = 0; i < 4; ++i) {
            float v = tt[tx][ty + i * 8];
            size_t o = (size_t)(n0 + ty + i * 8) * ldT + koff + k0 + tx;
            Th[o] = __float2half_rn(v);
        }
    } else if (bid < SU_LN) {
        const int row = bid - SU_PREP;
        const float* xr = x + (size_t)row * Hd;
        float v[4];
        float s = 0.f, s2 = 0.f;
#pragma unroll
        for (int i = 0; i < 4; ++i) {
            v[i] = xr[tid + i * 256];
            s += v[i]; s2 += v[i] * v[i];
        }
        __shared__ float red0[8], red1[8];
        const int lane = tid & 31, wid = tid >> 5;
#pragma unroll
        for (int o = 16; o > 0; o >>= 1) {
            s  += __shfl_xor_sync(0xffffffffu, s, o);
            s2 += __shfl_xor_sync(0xffffffffu, s2, o);
        }
        if (lane == 0) { red0[wid] = s; red1[wid] = s2; }
        __syncthreads();
        __shared__ float s_mean, s_rstd;
        if (tid == 0) {
            float ts = 0.f, ts2 = 0.f;
#pragma unroll
            for (int i = 0; i < 8; ++i) { ts += red0[i]; ts2 += red1[i]; }
            float mean = ts * (1.0f / Hd);
            float var  = ts2 * (1.0f / Hd) - mean * mean;
            s_mean = mean; s_rstd = rsqrtf(var + 1e-5f);
        }
        __syncthreads();
        const float mean = s_mean, rstd = s_rstd;
        __half* hrow = chi + (size_t)row * C2H;
#pragma unroll
        for (int i = 0; i < 4; ++i) {
            int c = tid + i * 256;
            hrow[c] = __float2half_rn((v[i] - mean) * rstd * gamma[c] + beta[c]);
        }
    } else if (bid < SU_SPL) {
        int i = (bid - SU_LN) * 256 + tid;
        p2[i] = __float2half_rn(proto[i]);
    } else {
        const int lin = bid - SU_SPL;
        const int bx = lin % 33, b = lin / 33;
        const int j = bx * 256 + tid;
        __shared__ float as[Hd];
        for (int i = tid; i < Hd; i += 256) as[i] = anchor[(size_t)b * Hd + i];
        __syncthreads();
        if (j >= 4*2048 + Ee) return;
        const float* wp; int stride; float* outp; float bia;
        if (j < 4*2048) {
            int pe = j >> 11, col = j & 2047;
            if (pe < 3) {
                wp = ew1 + (size_t)pe*3072*RHd + (size_t)2048*RHd + col; stride = RHd;
                bia = eb1[(size_t)pe * RHd + col];
            } else {
                if (col >= Hd) return;
                wp = gw1 + (size_t)2048*Hd + col; stride = Hd;
                bia = gb1[col];
            }
            outp = aux + (size_t)(pe*8 + b)*2048 + col;
        } else {
            int col = j - 4*2048;
            wp = routerW + (size_t)2048*Ee + col; stride = Ee;
            bia = routerB[col];
            outp = aux + AUX_ARL + b*Ee + col;
        }
        float acc = bia;
#pragma unroll 4
        for (int kk = 0; kk < Hd; ++kk) acc += as[kk] * wp[(size_t)kk * stride];
        *outp = acc;
    }
}

// ===========================================================================
// Cross-attention, 8 tokens / block
// ===========================================================================
__global__ __launch_bounds__(256)
void attn8_kernel(const float* __restrict__ q,
                  const float* __restrict__ kv,
                  __half* __restrict__ chi)
{
    const int t0  = blockIdx.x * 8;
    const int b   = t0 >> 11;
    const int tid = threadIdx.x;
    const int lane = tid & 31, w = tid >> 5;

    __shared__ float qs[8][Hd];
    __shared__ float sc[8][Pp];

    for (int i = tid; i < 8 * Hd; i += 256)
        qs[i >> 10][i & 1023] = q[(size_t)(t0 + (i >> 10)) * Hd + (i & 1023)];
    __syncthreads();

    const float* kvb = kv + (size_t)b * Pp * C2H;
    for (int p = w; p < Pp; p += 8) {
        const float* kr = kvb + (size_t)p * C2H;
        float d[8];
#pragma unroll
        for (int t = 0; t < 8; ++t) d[t] = 0.f;
        for (int i = lane; i < Hd; i += 32) {
            float kvv = kr[i];
#pragma unroll
            for (int t = 0; t < 8; ++t) d[t] += kvv * qs[t][i];
        }
#pragma unroll
        for (int t = 0; t < 8; ++t) {
#pragma unroll
            for (int o = 16; o > 0; o >>= 1)
                d[t] += __shfl_xor_sync(0xffffffffu, d[t], o);
        }
        if (lane == 0) {
#pragma unroll
            for (int t = 0; t < 8; ++t) sc[t][p] = d[t] * 0.03125f;
        }
    }
    __syncthreads();

    {
        float a = sc[w][lane], c = sc[w][lane + 32];
        float m = fmaxf(a, c);
#pragma unroll
        for (int o = 16; o > 0; o >>= 1) m = fmaxf(m, __shfl_xor_sync(0xffffffffu, m, o));
        float e1 = expf(a - m), e2 = expf(c - m);
        float ssum = e1 + e2;
#pragma unroll
        for (int o = 16; o > 0; o >>= 1) ssum += __shfl_xor_sync(0xffffffffu, ssum, o);
        float inv = 1.0f / ssum;
        sc[w][lane] = e1 * inv; sc[w][lane + 32] = e2 * inv;
    }
    __syncthreads();

    const int c0 = tid * 4;
    const float* vb = kvb + Hd + c0;
    float acc[8][4];
#pragma unroll
    for (int t = 0; t < 8; ++t)
#pragma unroll
        for (int j = 0; j < 4; ++j) acc[t][j] = 0.f;
    for (int p = 0; p < Pp; ++p) {
        float4 vv = *(const float4*)(vb + (size_t)p * C2H);
#pragma unroll
        for (int t = 0; t < 8; ++t) {
            float wt = sc[t][p];
            acc[t][0] += wt * vv.x; acc[t][1] += wt * vv.y;
            acc[t][2] += wt * vv.z; acc[t][3] += wt * vv.w;
        }
    }
#pragma unroll
    for (int t = 0; t < 8; ++t) {
        size_t base = (size_t)(t0 + t) * C2H + Hd + c0;
#pragma unroll
        for (int j = 0; j < 4; ++j)
            chi[base + j] = __float2half_rn(acc[t][j]);
    }
}

// ===========================================================================
// Router (fp16 combined)
// ===========================================================================
__global__ __launch_bounds__(128)
void router_kernel(const __half* __restrict__ chi,
                   const float* __restrict__ W,
                   const float* __restrict__ aux,
                   float* __restrict__ probs)
{
    const int row = blockIdx.x;
    const int b   = row >> 11;
    const int tid = threadIdx.x;
    const int lane = tid & 31, w = tid >> 5;
    __shared__ float lg[Ee];

    if (w < Ee) {
        const __half* cr = chi + (size_t)row * C2H;
        float d = 0.f;
        for (int i = lane; i < C2H; i += 32)
            d += __half2float(cr[i]) * W[(size_t)i * Ee + w];
#pragma unroll
        for (int o = 16; o > 0; o >>= 1) d += __shfl_xor_sync(0xffffffffu, d, o);
        if (lane == 0) lg[w] = d + aux[AUX_ARL + b*Ee + w];
    }
    __syncthreads();
    if (tid == 0) {
        float m = fmaxf(lg[0], fmaxf(lg[1], lg[2]));
        float e0 = expf(lg[0] - m), e1 = expf(lg[1] - m), e2 = expf(lg[2] - m);
        float inv = 1.0f / (e0 + e1 + e2);
        probs[(size_t)row * Ee + 0] = e0 * inv;
        probs[(size_t)row * Ee + 1] = e1 * inv;
        probs[(size_t)row * Ee + 2] = e2 * inv;
    }
}

// ===========================================================================
// GEMM body (round-14 mainloop)
// ===========================================================================
#define MAT_SZ   8192
#define STG_SZ   16384
#define SMEM_DYN 65536

struct GemmP {
    const __half* A; int lda;
    const __half* B; int K;
    float* C; int ldc;
    __half* Chi;
    const float* bias;
    const float* extra;
    const float* prob;
    const float* gate;
    const float* resid;
    int gx;
};

template<int EPI>
__device__ __forceinline__ void gemm_body(const GemmP g, int bx, int by)
{
    extern __shared__ char smem[];
    const uint32_t sb = smem_u32(smem);

    const int tid  = threadIdx.x;
    const int lane = tid & 31, wid = tid >> 5;
    const int bm = by * 128, bn = bx * 128;
    const int m0 = (wid >> 1) * 32, n0 = (wid & 1) * 64;

    const int rowA = tid >> 2, segA = tid & 3;
    const char* gA = (const char*)(g.A + (size_t)(bm + rowA) * g.lda + segA * 8);
    const char* gB = (const char*)(g.B + (size_t)(bn + rowA) * g.K + segA * 8);
    const size_t oA64 = (size_t)g.lda * 128;
    const size_t oB64 = (size_t)g.K * 128;
    const uint32_t sd0 = sb + rowA * 64 + ((segA ^ ((rowA >> 1) & 3)) << 4);

    const int NC = g.K >> 5;

#define ISSUE(it) do{ \
        if ((it) < NC) { \
            uint32_t so_ = sd0 + ((it) & 3) * STG_SZ; \
            CPA(so_,                  gA); \
            CPA(so_ + 4096,           gA + oA64); \
            CPA(so_ + MAT_SZ,         gB); \
            CPA(so_ + MAT_SZ + 4096,  gB + oB64); \
            gA += 64; gB += 64; \
        } \
        CPC(); \
    } while(0)

    ISSUE(0);
    ISSUE(1);
    ISSUE(2);

    float acc[2][8][4];
#pragma unroll
    for (int mi = 0; mi < 2; ++mi)
#pragma unroll
        for (int nt = 0; nt < 8; ++nt)
#pragma unroll
            for (int r = 0; r < 4; ++r) acc[mi][nt][r] = 0.f;

    const int arow = m0 + (lane & 15);
    const uint32_t abc = (uint32_t)(lane >> 4);
    uint32_t aro[2], asw[2];
#pragma unroll
    for (int mi = 0; mi < 2; ++mi) {
        int r = arow + mi * 16;
        aro[mi] = (uint32_t)(r * 64);
        asw[mi] = (uint32_t)((r >> 1) & 3);
    }
    const int brow = n0 + ((lane >> 4) & 1) * 8 + (lane & 7);
    const uint32_t bbc = (uint32_t)((lane >> 3) & 1);
    uint32_t bro[4], bsw[4];
#pragma unroll
    for (int p = 0; p < 4; ++p) {
        int r = brow + p * 16;
        bro[p] = (uint32_t)(MAT_SZ + r * 64);
        bsw[p] = (uint32_t)((r >> 1) & 3);
    }

    for (int it = 0; it < NC; ++it) {
        const uint32_t stg = sb + (it & 3) * STG_SZ;
        CPW2();
        __syncthreads();
        ISSUE(it + 3);

#pragma unroll
        for (int ks = 0; ks < 2; ++ks) {
            const uint32_t ks2 = (uint32_t)(ks << 1);
            uint32_t ah[2][4];
#pragma unroll
            for (int mi = 0; mi < 2; ++mi) {
                uint32_t ad = stg + aro[mi] + (((abc | ks2) ^ asw[mi]) << 4);
                ldsm4(ah[mi], ad);
            }
            uint32_t bh[16];
#pragma unroll
            for (int p = 0; p < 4; ++p) {
                uint32_t bd = stg + bro[p] + (((bbc | ks2) ^ bsw[p]) << 4);
                ldsm4(bh + p * 4, bd);
            }
#pragma unroll
            for (int mi = 0; mi < 2; ++mi)
#pragma unroll
                for (int nt = 0; nt < 8; ++nt)
                    mma16816(acc[mi][nt], ah[mi], bh + nt * 2);
        }
    }
    CPW0();

    // ---- epilogue ----
    const int pe = bn >> 11;
#pragma unroll
    for (int nt = 0; nt < 8; ++nt) {
        const int col = bn + n0 + nt * 8 + (lane & 3) * 2;
        float bia0 = 0.f, bia1 = 0.f;
        if (EPI == 3 || EPI == 4) { bia0 = g.bias[col]; bia1 = g.bias[col + 1]; }
#pragma unroll
        for (int mi = 0; mi < 2; ++mi) {
#pragma unroll
            for (int hf = 0; hf < 2; ++hf) {
                const int row = bm + m0 + mi * 16 + (lane >> 2) + hf * 8;
                float v0 = acc[mi][nt][hf * 2 + 0];
                float v1 = acc[mi][nt][hf * 2 + 1];
                const size_t off = (size_t)row * g.ldc + col;
                if (EPI == 0) {
                    *(float2*)(g.C + off) = make_float2(v0, v1);
                } else if (EPI == 1) {
                    const int b = row >> 11;
                    const float* ex = g.extra + ((size_t)(pe * 8 + b) << 11) + (col & 2047);
                    float s0 = siluf(v0 + ex[0]);
                    float s1 = siluf(v1 + ex[1]);
                    if (pe < 3) {
                        float p = g.prob[(size_t)row * Ee + pe];
                        s0 *= p; s1 *= p;
                    }
                    __half2 hv; hv.x = __float2half_rn(s0); hv.y = __float2half_rn(s1);
                    *(__half2*)(g.Chi + off) = hv;
                } else if (EPI == 2) {
                    float p0 = g.prob[(size_t)row * Ee + 0];
                    float p1 = g.prob[(size_t)row * Ee + 1];
                    float p2 = g.prob[(size_t)row * Ee + 2];
                    float u0 = v0 + p0*g.bias[col]   + p1*g.bias[Hd+col]   + p2*g.bias[2*Hd+col];
                    float u1 = v1 + p0*g.bias[col+1] + p1*g.bias[Hd+col+1] + p2*g.bias[2*Hd+col+1];
                    __half2 hv; hv.x = __float2half_rn(u0); hv.y = __float2half_rn(u1);
                    *(__half2*)(g.Chi + off) = hv;
                } else if (EPI == 3) {
                    *(float2*)(g.C + off) = make_float2(sigmf(v0 + bia0), sigmf(v1 + bia1));
                } else {
                    float2 gg = *(const float2*)(g.gate + off);
                    float2 xx = *(const float2*)(g.resid + off);
                    *(float2*)(g.C + off) =
                        make_float2(xx.x + gg.x * (v0 + bia0), xx.y + gg.y * (v1 + bia1));
                }
            }
        }
    }
#undef ISSUE
}

template<int EPI>
__global__ __launch_bounds__(256, 2)
void single_gemm(GemmP g)
{
    gemm_body<EPI>(g, blockIdx.x % g.gx, blockIdx.x / g.gx);
}

template<int E0, int E1>
__global__ __launch_bounds__(256, 2)
void dual_gemm(GemmP a, GemmP b, int split)
{
    const int bid = blockIdx.x;
    if (bid < split) {
        gemm_body<E0>(a, bid % a.gx, bid / a.gx);
    } else {
        const int l = bid - split;
        gemm_body<E1>(b, l % b.gx, l / b.gx);
    }
}

// ===========================================================================
// Launch (7 launches)
// ===========================================================================
extern "C" void kernel_launch(void* const* d_in, const int* in_sizes, int n_in,
                              void* d_out, int out_size)
{
    const float* x       = (const float*)d_in[0];
    const float* anchor  = (const float*)d_in[1];
    const float* proto   = (const float*)d_in[2];
    const float* gamma   = (const float*)d_in[3];
    const float* beta    = (const float*)d_in[4];
    const float* Wq      = (const float*)d_in[5];
    const float* Wk      = (const float*)d_in[6];
    const float* Wv      = (const float*)d_in[7];
    const float* routerW = (const float*)d_in[8];
    const float* routerB = (const float*)d_in[9];
    const float* ew1     = (const float*)d_in[10];
    const float* eb1     = (const float*)d_in[11];
    const float* ew2     = (const float*)d_in[12];
    const float* eb2     = (const float*)d_in[13];
    const float* gw1     = (const float*)d_in[14];
    const float* gb1     = (const float*)d_in[15];
    const float* gw2     = (const float*)d_in[16];
    const float* gb2     = (const float*)d_in[17];
    const float* outw    = (const float*)d_in[18];
    const float* outb    = (const float*)d_in[19];
    float* out = (float*)d_out;

    float *q, *kv, *gate, *probs, *aux;
    __half *c2, *h2, *r2, *p2, *wt;
    cudaGetSymbolAddress((void**)&c2, g_c);
    cudaGetSymbolAddress((void**)&h2, g_h);
    cudaGetSymbolAddress((void**)&r2, g_r);
    cudaGetSymbolAddress((void**)&p2, g_p);
    cudaGetSymbolAddress((void**)&q, g_q);
    cudaGetSymbolAddress((void**)&kv, g_kv);
    cudaGetSymbolAddress((void**)&gate, g_gate);
    cudaGetSymbolAddress((void**)&probs, g_probs);
    cudaGetSymbolAddress((void**)&aux, g_aux);
    cudaGetSymbolAddress((void**)&wt, g_wT);

    cudaFuncSetAttribute((const void*)single_gemm<1>, cudaFuncAttributeMaxDynamicSharedMemorySize, SMEM_DYN);
    cudaFuncSetAttribute((const void*)single_gemm<4>, cudaFuncAttributeMaxDynamicSharedMemorySize, SMEM_DYN);
    cudaFuncSetAttribute((const void*)dual_gemm<0,0>, cudaFuncAttributeMaxDynamicSharedMemorySize, SMEM_DYN);
    cudaFuncSetAttribute((const void*)dual_gemm<2,3>, cudaFuncAttributeMaxDynamicSharedMemorySize, SMEM_DYN);

    // 1: fused setup
    setup_all<<<SU_ANC, 256>>>(x, gamma, beta, proto, anchor,
                               Wq, Wk, Wv, routerW, routerB,
                               ew1, eb1, ew2, gw1, gb1, gw2, outw,
                               wt, c2, p2, aux);

    // 2: q ‖ kv projections (dual; kv needs 64 CTAs: 16 x 4)
    {
        GemmP a = { c2, C2H, wt + WQ_OFF, Hd, q, Hd, nullptr,
                    nullptr, nullptr, nullptr, nullptr, nullptr, Hd/128 };
        GemmP b = { p2, Hd, wt + WK_OFF, Hd, kv, C2H, nullptr,
                    nullptr, nullptr, nullptr, nullptr, nullptr, C2H/128 };
        dual_gemm<0,0><<<1024 + 64, 256, SMEM_DYN>>>(a, b, 1024);
    }

    // 3: attention
    attn8_kernel<<<BT/8, 256>>>(q, kv, c2);

    // 4: router
    router_kernel<<<BT, 128>>>(c2, routerW, aux, probs);

    // 5: fused up-projection [experts*3 | gate1]
    {
        GemmP a = { c2, C2H, wt + UP_OFF, C2H, nullptr, CUP, h2,
                    nullptr, aux, probs, nullptr, nullptr, CUP/128 };
        single_gemm<1><<<(CUP/128) * (BT/128), 256, SMEM_DYN>>>(a);
    }

    // 6: expert down ‖ gate2 (dual)
    {
        GemmP a = { h2, CUP, wt + EW2_OFF, CK6, nullptr, Hd, r2,
                    eb2, nullptr, probs, nullptr, nullptr, Hd/128 };
        GemmP b = { h2 + 6144, CUP, wt + GW2_OFF, Hd, gate, Hd, nullptr,
                    gb2, nullptr, nullptr, nullptr, nullptr, Hd/128 };
        dual_gemm<2,3><<<2048, 256, SMEM_DYN>>>(a, b, 1024);
    }

    // 7: final
    {
        GemmP a = { r2, Hd, wt + OW_OFF, Hd, out, Hd, nullptr,
                    outb, nullptr, nullptr, gate, x, Hd/128 };
        single_gemm<4><<<(Hd/128) * (BT/128), 256, SMEM_DYN>>>(a);
    }
}